// round 15
// baseline (speedup 1.0000x reference)
#include <cuda_runtime.h>
#include <cuda_fp16.h>
#include <cstdint>

#define N_NODES 50000
#define N_EDGES 800000
#define F_IN    256
#define F_HID   128
#define F_OUT   40

#define SCAN_B  256
#define NB      ((N_NODES + SCAN_B - 1) / SCAN_B)   // 196

// Scratch (no allocation allowed anywhere). All zero at module load;
// scan1 restores deg/cnt to zero each run so graph replays are identical.
__device__ float  g_deg  [N_NODES];
__device__ float  g_dinv [N_NODES];
__device__ int    g_cnt  [N_NODES];
__device__ int    g_ptr  [N_NODES + 1];
__device__ int    g_cur  [N_NODES];
__device__ int    g_bsum [NB];
__device__ int2   g_edge [N_EDGES];          // (src row, coef bits) per sorted slot
__device__ float  g_w1t  [F_HID * F_IN];     // W1^T, tf32-RNA: [128][256]
__device__ __half g_hh   [N_NODES * F_HID];  // layer1 linear output (fp16)
__device__ __half g_hrelu[N_NODES * F_HID];  // relu(agg1 + b1)  (fp16)
__device__ __half g_h2h  [N_NODES * F_OUT];  // layer2 linear output (fp16)

// ---------------------------------------------------------------------------
// TF32 / async helpers
// ---------------------------------------------------------------------------
__device__ __forceinline__ float to_tf32(float x) {
    uint32_t u;
    asm("cvt.rna.tf32.f32 %0, %1;" : "=r"(u) : "f"(x));
    return __uint_as_float(u);
}

__device__ __forceinline__ void mma_tf32(float* d, const uint32_t* a, const uint32_t* b) {
    asm volatile(
        "mma.sync.aligned.m16n8k8.row.col.f32.tf32.tf32.f32 "
        "{%0,%1,%2,%3}, {%4,%5,%6,%7}, {%8,%9}, {%0,%1,%2,%3};"
        : "+f"(d[0]), "+f"(d[1]), "+f"(d[2]), "+f"(d[3])
        : "r"(a[0]), "r"(a[1]), "r"(a[2]), "r"(a[3]),
          "r"(b[0]), "r"(b[1]));
}

__device__ __forceinline__ void ldsm_x4(uint32_t* r, uint32_t saddr) {
    asm volatile(
        "ldmatrix.sync.aligned.m8n8.x4.shared.b16 {%0,%1,%2,%3}, [%4];"
        : "=r"(r[0]), "=r"(r[1]), "=r"(r[2]), "=r"(r[3])
        : "r"(saddr));
}

__device__ __forceinline__ void cp_async16(uint32_t saddr, const void* gptr, int src_sz) {
    asm volatile("cp.async.cg.shared.global [%0], [%1], 16, %2;"
                 :: "r"(saddr), "l"(gptr), "r"(src_sz));
}
__device__ __forceinline__ void cp_commit() {
    asm volatile("cp.async.commit_group;");
}
template<int N>
__device__ __forceinline__ void cp_wait() {
    asm volatile("cp.async.wait_group %0;" :: "n"(N));
}

// ---------------------------------------------------------------------------
// W1 transpose + RNA tf32 round: [256][128] -> [128][256]
// ---------------------------------------------------------------------------
__global__ void transpose_w1_kernel(const float* __restrict__ W1,
                                    float* __restrict__ Wt)
{
    __shared__ float t[32][33];
    const int x = threadIdx.x & 31;
    const int y = threadIdx.x >> 5;
    const int k0 = blockIdx.x * 32;
    const int n0 = blockIdx.y * 32;
    #pragma unroll
    for (int i = 0; i < 4; ++i)
        t[y + i * 8][x] = W1[(k0 + y + i * 8) * F_HID + n0 + x];
    __syncthreads();
    #pragma unroll
    for (int i = 0; i < 4; ++i)
        Wt[(n0 + y + i * 8) * F_IN + k0 + x] = to_tf32(t[x][y + i * 8]);
}

// ---------------------------------------------------------------------------
// CSR build branch (forked stream). dinv = rsqrt(deg + 1): self-loop folded.
// ---------------------------------------------------------------------------
__global__ void count_kernel(const int* __restrict__ col,
                             const float* __restrict__ ew) {
    int i = (blockIdx.x * blockDim.x + threadIdx.x) * 2;   // N_EDGES is even
    if (i < N_EDGES) {
        int2   c = *(const int2*)(col + i);
        float2 w = *(const float2*)(ew + i);
        atomicAdd(&g_deg[c.x], w.x);
        atomicAdd(&g_cnt[c.x], 1);
        atomicAdd(&g_deg[c.y], w.y);
        atomicAdd(&g_cnt[c.y], 1);
    }
}

// block-level exclusive scan of g_cnt (warp-shuffle) + fused dinv + state reset
__global__ void scan1_kernel() {
    const int i    = blockIdx.x * SCAN_B + threadIdx.x;
    const int lane = threadIdx.x & 31;
    const int wid  = threadIdx.x >> 5;

    int v = 0;
    if (i < N_NODES) {
        v = g_cnt[i];
        float d = g_deg[i];
        g_dinv[i] = rsqrtf(d + 1.0f);
        g_deg[i] = 0.0f;
        g_cnt[i] = 0;
    }

    int x = v;
    #pragma unroll
    for (int o = 1; o < 32; o <<= 1) {
        int t = __shfl_up_sync(0xffffffffu, x, o);
        if (lane >= o) x += t;
    }
    __shared__ int wsum[8];
    if (lane == 31) wsum[wid] = x;
    __syncthreads();
    if (wid == 0) {
        int w = (lane < 8) ? wsum[lane] : 0;
        #pragma unroll
        for (int o = 1; o < 8; o <<= 1) {
            int t = __shfl_up_sync(0xffffffffu, w, o);
            if (lane >= o) w += t;
        }
        if (lane < 8) wsum[lane] = w;
    }
    __syncthreads();
    int incl = x + (wid > 0 ? wsum[wid - 1] : 0);
    if (i < N_NODES) g_ptr[i] = incl - v;
    if (threadIdx.x == SCAN_B - 1) g_bsum[blockIdx.x] = incl;
}

__global__ void scan3_kernel() {
    __shared__ int ws[8];
    const int t    = threadIdx.x;
    const int lane = t & 31;
    const int wid  = t >> 5;

    int v = (t < (int)blockIdx.x) ? g_bsum[t] : 0;
    #pragma unroll
    for (int o = 16; o > 0; o >>= 1) v += __shfl_down_sync(0xffffffffu, v, o);
    if (lane == 0) ws[wid] = v;
    __syncthreads();
    if (t == 0) {
        int s = 0;
        #pragma unroll
        for (int w = 0; w < 8; ++w) s += ws[w];
        ws[0] = s;
    }
    __syncthreads();
    int off = ws[0];

    int i = blockIdx.x * SCAN_B + t;
    if (i < N_NODES) {
        int p = g_ptr[i] + off;
        g_ptr[i] = p;
        g_cur[i] = p;
    }
    if (i == 0) g_ptr[N_NODES] = N_EDGES;
}

__global__ void fill_kernel(const int* __restrict__ row,
                            const int* __restrict__ col,
                            const float* __restrict__ ew) {
    int i = (blockIdx.x * blockDim.x + threadIdx.x) * 2;   // N_EDGES is even
    if (i < N_EDGES) {
        int2   r = *(const int2*)(row + i);
        int2   c = *(const int2*)(col + i);
        float2 w = *(const float2*)(ew + i);

        int pos0 = atomicAdd(&g_cur[c.x], 1);
        g_edge[pos0] = make_int2(r.x, __float_as_int(g_dinv[r.x] * w.x * g_dinv[c.x]));
        int pos1 = atomicAdd(&g_cur[c.y], 1);
        g_edge[pos1] = make_int2(r.y, __float_as_int(g_dinv[r.y] * w.y * g_dinv[c.y]));
    }
}

// ---------------------------------------------------------------------------
// GEMM1 (cp.async, 3-stage + ldmatrix): C[M,128] = A[M,256] @ W1, fp16 out.
// ---------------------------------------------------------------------------
#define G1_BM  128
#define G1_BK  32
#define G1_STR 36
#define G1_ASZ (G1_BM * G1_STR)
#define G1_BSZ (F_HID * G1_STR)
#define G1_STG (G1_ASZ + G1_BSZ)
#define G1_NSTAGE 3

__global__ __launch_bounds__(256, 2)
void gemm1_cpasync_kernel(const float* __restrict__ A,
                          const float* __restrict__ Bt,
                          __half* __restrict__ C, int M)
{
    extern __shared__ float sm[];

    const int tid  = threadIdx.x;
    const int wid  = tid >> 5;
    const int lane = tid & 31;
    const int gid  = lane >> 2;
    const int tig  = lane & 3;
    const int wm   = wid & 3;
    const int wn   = wid >> 2;
    const int m0   = blockIdx.x * G1_BM;

    const int lr = lane & 7;
    const int lg = lane >> 3;
    const int aRow = (lg & 1) * 8 + lr;
    const int aKof = (lg >> 1) * 4;
    const int bRow = (lg >> 1) * 8 + lr;
    const int bKof = (lg & 1) * 4;

    const uint32_t sBase = (uint32_t)__cvta_generic_to_shared(sm);

    const int am  = tid >> 1;
    const int akq = (tid & 1) * 4;
    const int grA = m0 + am;
    const int aOk = (grA < M) ? 16 : 0;
    const long long aGof = (long long)min(grA, M - 1) * F_IN;

    auto stage_load = [&](int it, int s) {
        uint32_t sA = sBase + (uint32_t)(s * G1_STG) * 4u;
        uint32_t sB = sA + (uint32_t)G1_ASZ * 4u;
        #pragma unroll
        for (int h = 0; h < 4; ++h) {
            int kq = akq + h;
            cp_async16(sA + (uint32_t)(am * G1_STR + kq * 4) * 4u,
                       A + aGof + it * G1_BK + kq * 4, aOk);
        }
        #pragma unroll
        for (int j = 0; j < 4; ++j) {
            int f = j * 256 + tid;
            int n = f >> 3, kq = f & 7;
            cp_async16(sB + (uint32_t)(n * G1_STR + kq * 4) * 4u,
                       Bt + (size_t)n * F_IN + it * G1_BK + kq * 4, 16);
        }
    };

    float acc[2][8][4];
    #pragma unroll
    for (int mi = 0; mi < 2; ++mi)
        #pragma unroll
        for (int ni = 0; ni < 8; ++ni)
            #pragma unroll
            for (int e = 0; e < 4; ++e)
                acc[mi][ni][e] = 0.f;

    stage_load(0, 0); cp_commit();
    stage_load(1, 1); cp_commit();
    stage_load(2, 2); cp_commit();
    cp_wait<2>();
    __syncthreads();

    constexpr int ITERS = F_IN / G1_BK;   // 8
    for (int it = 0; it < ITERS; ++it) {
        const int s = it % G1_NSTAGE;
        const uint32_t sA = sBase + (uint32_t)(s * G1_STG) * 4u;
        const uint32_t sB = sA + (uint32_t)G1_ASZ * 4u;

        #pragma unroll
        for (int kk = 0; kk < G1_BK; kk += 8) {
            uint32_t af[2][4];
            #pragma unroll
            for (int mi = 0; mi < 2; ++mi) {
                int m = wm * 32 + mi * 16 + aRow;
                ldsm_x4(af[mi], sA + (uint32_t)(m * G1_STR + kk + aKof) * 4u);
            }
            uint32_t bf[4][4];
            #pragma unroll
            for (int nj = 0; nj < 4; ++nj) {
                int n = wn * 64 + nj * 16 + bRow;
                ldsm_x4(bf[nj], sB + (uint32_t)(n * G1_STR + kk + bKof) * 4u);
            }
            #pragma unroll
            for (int mi = 0; mi < 2; ++mi)
                #pragma unroll
                for (int nj = 0; nj < 4; ++nj) {
                    mma_tf32(acc[mi][nj * 2    ], af[mi], &bf[nj][0]);
                    mma_tf32(acc[mi][nj * 2 + 1], af[mi], &bf[nj][2]);
                }
        }

        if (it + 1 < ITERS) {
            __syncthreads();
            if (it + 3 < ITERS) {
                stage_load(it + 3, s); cp_commit();
                cp_wait<2>();
            } else if (it + 2 < ITERS) {
                cp_wait<1>();
            } else {
                cp_wait<0>();
            }
            __syncthreads();
        }
    }

    #pragma unroll
    for (int mi = 0; mi < 2; ++mi) {
        #pragma unroll
        for (int ni = 0; ni < 8; ++ni) {
            int col = wn * 64 + ni * 8 + tig * 2;
            int r0  = m0 + wm * 32 + mi * 16 + gid;
            int r1  = r0 + 8;
            if (r0 < M)
                *(__half2*)(C + (size_t)r0 * F_HID + col) =
                    __floats2half2_rn(acc[mi][ni][0], acc[mi][ni][1]);
            if (r1 < M)
                *(__half2*)(C + (size_t)r1 * F_HID + col) =
                    __floats2half2_rn(acc[mi][ni][2], acc[mi][ni][3]);
        }
    }
}

// ---------------------------------------------------------------------------
// GEMM2: C[M,40] = A[M,128](fp16) @ W2[128,40](fp32), tf32 MMA, fp16 out.
// A loaded as fp16, converted (exact) to float then RNA-tf32 at STS.
// BM=128 BN=64 BK=32.
// ---------------------------------------------------------------------------
#define G2_BM 128
#define G2_BN 64
#define G2_BK 32
#define G2_KT 128
#define G2_NA 40

__global__ void gemm2_kernel(const __half* __restrict__ A,
                             const float* __restrict__ B,
                             __half* __restrict__ C, int M)
{
    constexpr int WM = 32, WN = 32;      // 4 warps M x 2 warps N
    constexpr int ITERS = G2_KT / G2_BK; // 4

    __shared__ float As[G2_BK][G2_BM + 1];
    __shared__ float Bs[G2_BK][G2_BN + 4];

    const int tid  = threadIdx.x;
    const int wid  = tid >> 5;
    const int lane = tid & 31;
    const int gid  = lane >> 2;
    const int tig  = lane & 3;
    const int wm   = wid & 3;
    const int wn   = wid >> 2;
    const int m0   = blockIdx.x * G2_BM;

    // A: each thread owns row m = tid/2, halfs [koff, koff+16)
    const int am   = tid >> 1;
    const int koff = (tid & 1) * 16;
    const int grA  = m0 + am;

    __half aH[16];
    float4 bReg[2];

    auto ldg = [&](int it) {
        if (grA < M) {
            const __half* src = A + (size_t)grA * G2_KT + it * G2_BK + koff;
            *(uint4*)&aH[0] = *(const uint4*)(src);
            *(uint4*)&aH[8] = *(const uint4*)(src + 8);
        } else {
            #pragma unroll
            for (int j = 0; j < 16; ++j) aH[j] = __float2half(0.f);
        }
        // B tile: 32 k x 64 n (40 active) = 512 float4 / 256 thr = 2
        #pragma unroll
        for (int j = 0; j < 2; ++j) {
            int f = j * 256 + tid;
            int k = f / (G2_BN / 4), nq = f % (G2_BN / 4);
            float v[4];
            #pragma unroll
            for (int e = 0; e < 4; ++e) {
                int n = nq * 4 + e;
                v[e] = (n < G2_NA) ? B[(size_t)(it * G2_BK + k) * G2_NA + n] : 0.f;
            }
            bReg[j] = make_float4(v[0], v[1], v[2], v[3]);
        }
    };

    auto sts = [&]() {
        #pragma unroll
        for (int j = 0; j < 16; ++j)
            As[koff + j][am] = to_tf32(__half2float(aH[j]));
        #pragma unroll
        for (int j = 0; j < 2; ++j) {
            int f = j * 256 + tid;
            int k = f / (G2_BN / 4), nq = f % (G2_BN / 4);
            float4 t;
            t.x = to_tf32(bReg[j].x); t.y = to_tf32(bReg[j].y);
            t.z = to_tf32(bReg[j].z); t.w = to_tf32(bReg[j].w);
            *(float4*)&Bs[k][nq * 4] = t;
        }
    };

    float acc[2][4][4];
    #pragma unroll
    for (int mi = 0; mi < 2; ++mi)
        #pragma unroll
        for (int ni = 0; ni < 4; ++ni)
            #pragma unroll
            for (int e = 0; e < 4; ++e)
                acc[mi][ni][e] = 0.f;

    ldg(0);
    sts();
    __syncthreads();

    for (int it = 0; it < ITERS; ++it) {
        if (it + 1 < ITERS) ldg(it + 1);

        #pragma unroll
        for (int kk = 0; kk < G2_BK; kk += 8) {
            uint32_t af[2][4];
            uint32_t bf[4][2];
            #pragma unroll
            for (int mi = 0; mi < 2; ++mi) {
                int mb = wm * WM + mi * 16;
                af[mi][0] = __float_as_uint(As[kk + tig    ][mb + gid    ]);
                af[mi][1] = __float_as_uint(As[kk + tig    ][mb + gid + 8]);
                af[mi][2] = __float_as_uint(As[kk + tig + 4][mb + gid    ]);
                af[mi][3] = __float_as_uint(As[kk + tig + 4][mb + gid + 8]);
            }
            #pragma unroll
            for (int ni = 0; ni < 4; ++ni) {
                int nb = wn * WN + ni * 8;
                bf[ni][0] = __float_as_uint(Bs[kk + tig    ][nb + gid]);
                bf[ni][1] = __float_as_uint(Bs[kk + tig + 4][nb + gid]);
            }
            #pragma unroll
            for (int mi = 0; mi < 2; ++mi)
                #pragma unroll
                for (int ni = 0; ni < 4; ++ni)
                    mma_tf32(acc[mi][ni], af[mi], bf[ni]);
        }

        __syncthreads();
        if (it + 1 < ITERS) {
            sts();
            __syncthreads();
        }
    }

    #pragma unroll
    for (int mi = 0; mi < 2; ++mi) {
        #pragma unroll
        for (int ni = 0; ni < 4; ++ni) {
            int col = wn * WN + ni * 8 + tig * 2;
            if (col >= G2_NA) continue;
            int r0 = m0 + wm * WM + mi * 16 + gid;
            int r1 = r0 + 8;
            if (r0 < M)
                *(__half2*)(C + (size_t)r0 * G2_NA + col) =
                    __floats2half2_rn(acc[mi][ni][0], acc[mi][ni][1]);
            if (r1 < M)
                *(__half2*)(C + (size_t)r1 * G2_NA + col) =
                    __floats2half2_rn(acc[mi][ni][2], acc[mi][ni][3]);
        }
    }
}

// ---------------------------------------------------------------------------
// Gather layer 1: h fp16, accumulate fp32, unroll 4, fp16 output.
// ---------------------------------------------------------------------------
__device__ __forceinline__ void fma_h4(float4& acc, uint2 raw, float c) {
    float2 p0 = __half22float2(*(__half2*)&raw.x);
    float2 p1 = __half22float2(*(__half2*)&raw.y);
    acc.x += p0.x * c; acc.y += p0.y * c;
    acc.z += p1.x * c; acc.w += p1.y * c;
}

__global__ void gather128_kernel(const __half* __restrict__ h,
                                 const float* __restrict__ b,
                                 __half* __restrict__ out)
{
    int node = (blockIdx.x * blockDim.x + threadIdx.x) >> 5;
    int lane = threadIdx.x & 31;
    if (node >= N_NODES) return;

    float g  = g_dinv[node];
    float gg = g * g;
    float4 acc;
    {
        uint2 raw = *(const uint2*)(h + (size_t)node * F_HID + lane * 4);
        float2 p0 = __half22float2(*(__half2*)&raw.x);
        float2 p1 = __half22float2(*(__half2*)&raw.y);
        acc.x = p0.x * gg; acc.y = p0.y * gg;
        acc.z = p1.x * gg; acc.w = p1.y * gg;
    }

    int e   = g_ptr[node];
    int end = g_ptr[node + 1];
    for (; e + 4 <= end; e += 4) {
        int2 e0 = g_edge[e],     e1 = g_edge[e + 1];
        int2 e2 = g_edge[e + 2], e3 = g_edge[e + 3];
        uint2 r0 = *(const uint2*)(h + (size_t)e0.x * F_HID + lane * 4);
        uint2 r1 = *(const uint2*)(h + (size_t)e1.x * F_HID + lane * 4);
        uint2 r2 = *(const uint2*)(h + (size_t)e2.x * F_HID + lane * 4);
        uint2 r3 = *(const uint2*)(h + (size_t)e3.x * F_HID + lane * 4);
        fma_h4(acc, r0, __int_as_float(e0.y));
        fma_h4(acc, r1, __int_as_float(e1.y));
        fma_h4(acc, r2, __int_as_float(e2.y));
        fma_h4(acc, r3, __int_as_float(e3.y));
    }
    for (; e < end; ++e) {
        int2 e0 = g_edge[e];
        uint2 r0 = *(const uint2*)(h + (size_t)e0.x * F_HID + lane * 4);
        fma_h4(acc, r0, __int_as_float(e0.y));
    }

    float4 bb = ((const float4*)b)[lane];
    __half2 o0 = __floats2half2_rn(fmaxf(acc.x + bb.x, 0.0f),
                                   fmaxf(acc.y + bb.y, 0.0f));
    __half2 o1 = __floats2half2_rn(fmaxf(acc.z + bb.z, 0.0f),
                                   fmaxf(acc.w + bb.w, 0.0f));
    uint2 ov;
    ov.x = *(uint32_t*)&o0;
    ov.y = *(uint32_t*)&o1;
    *(uint2*)(out + (size_t)node * F_HID + lane * 4) = ov;
}

// ---------------------------------------------------------------------------
// Final gather, F=40, fp16 source: lanes 0..19 own half2 feature pairs.
// ---------------------------------------------------------------------------
__global__ void gather40_kernel(const __half* __restrict__ h,
                                const float* __restrict__ b,
                                float* __restrict__ out)
{
    int node = (blockIdx.x * blockDim.x + threadIdx.x) >> 5;
    int lane = threadIdx.x & 31;
    if (node >= N_NODES) return;
    if (lane >= F_OUT / 2) return;

    float g  = g_dinv[node];
    float gg = g * g;

    float2 acc = __half22float2(*(const __half2*)(h + (size_t)node * F_OUT + lane * 2));
    acc.x *= gg; acc.y *= gg;

    int e   = g_ptr[node];
    int end = g_ptr[node + 1];
    for (; e + 2 <= end; e += 2) {
        int2 e0 = g_edge[e], e1 = g_edge[e + 1];
        float c0 = __int_as_float(e0.y);
        float c1 = __int_as_float(e1.y);
        float2 v0 = __half22float2(*(const __half2*)(h + (size_t)e0.x * F_OUT + lane * 2));
        float2 v1 = __half22float2(*(const __half2*)(h + (size_t)e1.x * F_OUT + lane * 2));
        acc.x += v0.x * c0 + v1.x * c1;
        acc.y += v0.y * c0 + v1.y * c1;
    }
    if (e < end) {
        int2 e0 = g_edge[e];
        float c0 = __int_as_float(e0.y);
        float2 v0 = __half22float2(*(const __half2*)(h + (size_t)e0.x * F_OUT + lane * 2));
        acc.x += v0.x * c0;
        acc.y += v0.y * c0;
    }

    float2 bb = ((const float2*)b)[lane];
    *(float2*)(out + (size_t)node * F_OUT + lane * 2) =
        make_float2(acc.x + bb.x, acc.y + bb.y);
}

// ---------------------------------------------------------------------------
extern "C" void kernel_launch(void* const* d_in, const int* in_sizes, int n_in,
                              void* d_out, int out_size)
{
    const float* x   = (const float*)d_in[0];
    const int*   ei  = (const int*)d_in[1];      // int64 ref -> int32 on device
    const float* ew  = (const float*)d_in[2];
    const float* W1  = (const float*)d_in[3];
    const float* b1  = (const float*)d_in[4];
    const float* W2  = (const float*)d_in[5];
    const float* b2  = (const float*)d_in[6];
    float*       out = (float*)d_out;

    const int* row = ei;
    const int* col = ei + N_EDGES;

    __half *p_hh, *p_h2h, *p_hrelu;
    float *p_w1t;
    cudaGetSymbolAddress((void**)&p_hh,    g_hh);
    cudaGetSymbolAddress((void**)&p_h2h,   g_h2h);
    cudaGetSymbolAddress((void**)&p_hrelu, g_hrelu);
    cudaGetSymbolAddress((void**)&p_w1t,   g_w1t);

    const int T = 256;
    const int GB_E2 = (N_EDGES / 2 + T - 1) / T;
    const int GB_W  = (N_NODES * 32 + T - 1) / T;
    const int GEMM_GRID = (N_NODES + 127) / 128;

    const int G1_SMEM = G1_NSTAGE * G1_STG * (int)sizeof(float);   // 110592 B
    cudaFuncSetAttribute(gemm1_cpasync_kernel,
                         cudaFuncAttributeMaxDynamicSharedMemorySize, G1_SMEM);

    // Fork a worker stream so the CSR build overlaps GEMM1.
    cudaStream_t s1;
    cudaEvent_t  eFork, eJoin;
    cudaStreamCreateWithFlags(&s1, cudaStreamNonBlocking);
    cudaEventCreateWithFlags(&eFork, cudaEventDisableTiming);
    cudaEventCreateWithFlags(&eJoin, cudaEventDisableTiming);

    cudaEventRecord(eFork, 0);
    cudaStreamWaitEvent(s1, eFork, 0);

    // GEMM1 stays 4th in host launch order (ncu profiles #4).
    transpose_w1_kernel<<<dim3(8, 4), 256>>>(W1, p_w1t);               // main (1)
    count_kernel<<<GB_E2, T, 0, s1>>>(col, ew);                        // s1   (2)
    scan1_kernel<<<NB, SCAN_B, 0, s1>>>();                             // s1   (3)

    gemm1_cpasync_kernel<<<GEMM_GRID, 256, G1_SMEM>>>(x, p_w1t, p_hh, N_NODES); // main (4)

    scan3_kernel<<<NB, SCAN_B, 0, s1>>>();                             // s1
    fill_kernel <<<GB_E2, T, 0, s1>>>(row, col, ew);                   // s1
    cudaEventRecord(eJoin, s1);

    cudaStreamWaitEvent(0, eJoin, 0);

    gather128_kernel<<<GB_W, T>>>(p_hh, b1, p_hrelu);

    gemm2_kernel<<<GEMM_GRID, 256>>>(p_hrelu, W2, p_h2h, N_NODES);
    gather40_kernel<<<GB_W, T>>>(p_h2h, b2, out);
}